// round 12
// baseline (speedup 1.0000x reference)
#include <cuda_runtime.h>
#include <cuda_fp16.h>
#include <cstdint>

// ---------------- problem constants ----------------
#define BQ    8
#define HWQ   6400          // 80*80
#define MTOT  51200         // 8*6400
#define K1    1024
#define N1    256
#define K2    256
#define N2    1024
#define NSEG  25            // 6400 / 256

// ---------------- scratch (device globals) --------
__device__ __align__(16) __half g_W1h[N1 * K1];      // [n][k] fp16 (DWT+BN1 folded)
__device__ __align__(16) float  g_bias1[N1];
__device__ __align__(16) __half g_W2h[N2 * K2];      // [j][k] fp16, j = c'*4+g (permuted)
__device__ __align__(16) float  g_bias2p[N2];
__device__ __align__(16) __half g_fused[(long)MTOT * 256];   // fp16 (26 MB)
__device__ __align__(16) float  g_avg_sp[MTOT];
__device__ __align__(16) float  g_max_sp[MTOT];
__device__ __align__(16) float  g_gate[MTOT];
__device__ __align__(16) float  g_chsum_part[NSEG * BQ * 256];
__device__ __align__(16) float  g_chmax_part[NSEG * BQ * 256];

// ---------------- PTX helpers ----------------------
__device__ __forceinline__ uint32_t smem_u32(const void* p) {
    uint32_t a;
    asm("{ .reg .u64 t; cvta.to.shared.u64 t, %1; cvt.u32.u64 %0, t; }" : "=r"(a) : "l"(p));
    return a;
}
__device__ __forceinline__ void ldsm4(uint32_t* r, uint32_t addr) {
    asm volatile("ldmatrix.sync.aligned.m8n8.x4.shared.b16 {%0,%1,%2,%3}, [%4];"
                 : "=r"(r[0]), "=r"(r[1]), "=r"(r[2]), "=r"(r[3]) : "r"(addr));
}
__device__ __forceinline__ void ldsm4t(uint32_t* r, uint32_t addr) {
    asm volatile("ldmatrix.sync.aligned.m8n8.x4.trans.shared.b16 {%0,%1,%2,%3}, [%4];"
                 : "=r"(r[0]), "=r"(r[1]), "=r"(r[2]), "=r"(r[3]) : "r"(addr));
}
__device__ __forceinline__ void mma16(float* d, const uint32_t* a, uint32_t b0, uint32_t b1) {
    asm volatile(
        "mma.sync.aligned.m16n8k16.row.col.f32.f16.f16.f32 "
        "{%0,%1,%2,%3}, {%4,%5,%6,%7}, {%8,%9}, {%0,%1,%2,%3};"
        : "+f"(d[0]), "+f"(d[1]), "+f"(d[2]), "+f"(d[3])
        : "r"(a[0]), "r"(a[1]), "r"(a[2]), "r"(a[3]), "r"(b0), "r"(b1));
}
__device__ __forceinline__ void cpa16(uint32_t dst, const void* src) {
    asm volatile("cp.async.cg.shared.global [%0], [%1], 16;" :: "r"(dst), "l"(src));
}
#define CP_COMMIT asm volatile("cp.async.commit_group;" ::: "memory")
#define CP_WAIT1  asm volatile("cp.async.wait_group 1;" ::: "memory")
#define CP_WAIT0  asm volatile("cp.async.wait_group 0;" ::: "memory")

// ---------------- prep: fold DWT+BN1 into W1; BN2+permute into W2 ---------
__global__ void prep(const float* __restrict__ fw, const float* __restrict__ fb,
                     const float* __restrict__ g1, const float* __restrict__ b1,
                     const float* __restrict__ m1, const float* __restrict__ v1,
                     const float* __restrict__ pw, const float* __restrict__ pb,
                     const float* __restrict__ g2, const float* __restrict__ b2,
                     const float* __restrict__ m2, const float* __restrict__ v2) {
    int idx = blockIdx.x * blockDim.x + threadIdx.x;
    if (idx < K1 * N1) {
        int o = idx & 255;
        int k = idx >> 8;            // k = c*4 + q, q = 2*dy + dx
        int c = k >> 2, q = k & 3;
        float inv = g1[o] * rsqrtf(v1[o] + 1e-5f);
        float slh = (q < 2) ? 1.f : -1.f;
        float shl = ((q & 1) == 0) ? 1.f : -1.f;
        float shh = slh * shl;
        float val = fw[o * 1024 + c]
                  + slh * fw[o * 1024 + 256 + c]
                  + shl * fw[o * 1024 + 512 + c]
                  + shh * fw[o * 1024 + 768 + c];
        g_W1h[o * 1024 + k] = __float2half_rn(0.5f * inv * val);
        if (k == 0) g_bias1[o] = fb[o] * inv + b1[o] - m1[o] * inv;
    } else {
        int idx2 = idx - K1 * N1;
        int j = idx2 & 1023;          // j = c'*4 + g
        int k = idx2 >> 10;
        int o = (j & 3) * 256 + (j >> 2);
        float inv = g2[o] * rsqrtf(v2[o] + 1e-5f);
        g_W2h[j * 256 + k] = __float2half_rn(pw[o * 256 + k] * inv);
        if (k == 0) g_bias2p[j] = pb[o] * inv + b2[o] - m2[o] * inv;
    }
}

// ============================================================================
// GEMM1 (fp16 HMMA k16): CTA 128m x 256n, 512 thr (16 warps 4m x 4n, warp
// tile 32x64), k-chunk 64 (16 chunks). A stored TRANSPOSED [k][m] (272B rows)
// -> conflict-free STS; A frags via ldmatrix.x4.trans. 3-stage A STS ring +
// 3-stage B cp.async ring, distance-2 waits.
// smem: A 3x17408 @0; B 3x36864 @52224; bias@162816(1024) redS@163840(2048)
//       redM@165888(2048)  total 167936
// ============================================================================
#define G1_SMEM 167936
__global__ __launch_bounds__(512) void gemm1(const float* __restrict__ x) {
    extern __shared__ char smem[];
    const uint32_t sb = smem_u32(smem);
    const int tid = threadIdx.x;
    const int lane = tid & 31, warp = tid >> 5;
    const int wm = warp & 3, wn = warp >> 2;
    const int m0 = blockIdx.x * 128;
    const int bb = m0 / HWQ;
    const int hw0 = m0 % HWQ;

    if (tid < 64) ((float4*)(smem + 162816))[tid] = ((const float4*)g_bias1)[tid];

    // ---- A gather setup (chunk ch covers channels ch*16 .. ch*16+15)
    const int cA = tid >> 7;             // 0..3 ; groups at cA, cA+4, cA+8, cA+12
    const int dyA = (tid >> 6) & 1;
    const int mlA = (tid & 63) * 2;      // even local m
    const int hwA = hw0 + mlA;
    const int hA = hwA / 80, wA = hwA - hA * 80;
    const float* aBase = x + (long)bb * 256 * 25600 + cA * 25600 + (2 * hA + dyA) * 160 + 2 * wA;
    const int aRowOff = (cA * 4 + dyA * 2) * 272 + mlA * 2;   // bytes

    // ---- B cp.async setup: 256 rows x 64 halves (128B) per chunk
    const int rowB = tid >> 1;
    const int colH = (tid & 1) * 32;
    const __half* bSrcBase = g_W1h + rowB * 1024 + colH;
    const uint32_t bDstOff = (uint32_t)(rowB * 144 + colH * 2);

    // ---- ldsm lane bases
    const uint32_t aLd = sb
        + (uint32_t)(((lane & 7) + ((lane >> 4) << 3)) * 272
                     + (wm * 32 + ((lane >> 3) & 1) * 8) * 2);
    const uint32_t bLd = sb + 52224u + (uint32_t)((wn * 64 + (lane & 15)) * 144 + (lane >> 4) * 16);

    float acc[2][8][4];
#pragma unroll
    for (int a = 0; a < 2; a++)
#pragma unroll
        for (int b = 0; b < 8; b++)
#pragma unroll
            for (int c = 0; c < 4; c++) acc[a][b][c] = 0.f;

    // ---- prologue: A(0) -> stage0; A(1) -> regs; B(0)->s0, B(1)->s1 in flight
    float4 aP[4];
#pragma unroll
    for (int i = 0; i < 4; ++i) aP[i] = *(const float4*)(aBase + i * 4 * 25600);
    {
        char* aSt = smem + aRowOff;
#pragma unroll
        for (int i = 0; i < 4; ++i) {
            *(__half2*)(aSt + i * 16 * 272)       = __floats2half2_rn(aP[i].x, aP[i].z);
            *(__half2*)(aSt + i * 16 * 272 + 272) = __floats2half2_rn(aP[i].y, aP[i].w);
        }
    }
#pragma unroll
    for (int i = 0; i < 4; ++i) aP[i] = *(const float4*)(aBase + 409600 + i * 4 * 25600);
    {
        uint32_t bD = sb + 52224u + bDstOff;
        const __half* bS = bSrcBase;
        cpa16(bD, bS); cpa16(bD + 16, bS + 8); cpa16(bD + 32, bS + 16); cpa16(bD + 48, bS + 24);
        CP_COMMIT;
        bD = sb + 52224u + 36864u + bDstOff;
        bS = bSrcBase + 64;
        cpa16(bD, bS); cpa16(bD + 16, bS + 8); cpa16(bD + 32, bS + 16); cpa16(bD + 48, bS + 24);
        CP_COMMIT;
    }

    for (int it = 0; it < 16; ++it) {
        if (it < 15) { CP_WAIT1; } else { CP_WAIT0; }
        __syncthreads();                       // A(it), B(it) visible; compute(it-1) retired
        if (it < 15) {                         // STS A(it+1) -> stage (it+1)%3 (conflict-free)
            char* aSt = smem + ((it + 1) % 3) * 17408 + aRowOff;
#pragma unroll
            for (int i = 0; i < 4; ++i) {
                *(__half2*)(aSt + i * 16 * 272)       = __floats2half2_rn(aP[i].x, aP[i].z);
                *(__half2*)(aSt + i * 16 * 272 + 272) = __floats2half2_rn(aP[i].y, aP[i].w);
            }
        }
        if (it < 14) {                         // B(it+2) -> stage (it+2)%3; A(it+2) -> regs
            uint32_t bD = sb + 52224u + (uint32_t)(((it + 2) % 3) * 36864) + bDstOff;
            const __half* bS = bSrcBase + (it + 2) * 64;
            cpa16(bD, bS); cpa16(bD + 16, bS + 8); cpa16(bD + 32, bS + 16); cpa16(bD + 48, bS + 24);
            CP_COMMIT;
#pragma unroll
            for (int i = 0; i < 4; ++i)
                aP[i] = *(const float4*)(aBase + (long)(it + 2) * 409600 + i * 4 * 25600);
        }
        const uint32_t aB = aLd + (uint32_t)((it % 3) * 17408);
        const uint32_t bB = bLd + (uint32_t)((it % 3) * 36864);
#pragma unroll
        for (int kk = 0; kk < 4; ++kk) {       // 4 x k16
            uint32_t af[2][4], bf[4][4];
            ldsm4t(af[0], aB + kk * 16 * 272);
            ldsm4t(af[1], aB + kk * 16 * 272 + 32);
#pragma unroll
            for (int i = 0; i < 4; ++i) ldsm4(bf[i], bB + kk * 32 + i * 16 * 144);
#pragma unroll
            for (int ms = 0; ms < 2; ++ms)
#pragma unroll
                for (int i = 0; i < 4; ++i) {
                    mma16(acc[ms][2 * i + 0], af[ms], bf[i][0], bf[i][2]);
                    mma16(acc[ms][2 * i + 1], af[ms], bf[i][1], bf[i][3]);
                }
        }
    }

    // ---- epilogue: bias+relu -> g_fused (fp16); full-row sum/max
    const float* biasS = (const float*)(smem + 162816);
    float* redS = (float*)(smem + 163840);
    float* redM = (float*)(smem + 165888);
    __half2* fh2 = (__half2*)g_fused;
    float rs[2][2] = {{0.f, 0.f}, {0.f, 0.f}};
    float rm[2][2] = {{0.f, 0.f}, {0.f, 0.f}};
#pragma unroll
    for (int ms = 0; ms < 2; ++ms) {
        int row0 = m0 + wm * 32 + ms * 16 + (lane >> 2);
#pragma unroll
        for (int ns = 0; ns < 8; ++ns) {
            int col = wn * 64 + ns * 8 + (lane & 3) * 2;
            float b0 = biasS[col], b1 = biasS[col + 1];
            float v0 = fmaxf(acc[ms][ns][0] + b0, 0.f);
            float v1 = fmaxf(acc[ms][ns][1] + b1, 0.f);
            fh2[(long)row0 * 128 + (col >> 1)] = __floats2half2_rn(v0, v1);
            rs[ms][0] += v0 + v1;
            rm[ms][0] = fmaxf(rm[ms][0], fmaxf(v0, v1));
            float v2 = fmaxf(acc[ms][ns][2] + b0, 0.f);
            float v3 = fmaxf(acc[ms][ns][3] + b1, 0.f);
            fh2[(long)(row0 + 8) * 128 + (col >> 1)] = __floats2half2_rn(v2, v3);
            rs[ms][1] += v2 + v3;
            rm[ms][1] = fmaxf(rm[ms][1], fmaxf(v2, v3));
        }
    }
#pragma unroll
    for (int ms = 0; ms < 2; ++ms)
#pragma unroll
        for (int hf = 0; hf < 2; ++hf) {
            float s = rs[ms][hf], mx = rm[ms][hf];
            s += __shfl_xor_sync(0xffffffffu, s, 1);
            s += __shfl_xor_sync(0xffffffffu, s, 2);
            mx = fmaxf(mx, __shfl_xor_sync(0xffffffffu, mx, 1));
            mx = fmaxf(mx, __shfl_xor_sync(0xffffffffu, mx, 2));
            if ((lane & 3) == 0) {
                int r_l = wm * 32 + ms * 16 + (lane >> 2) + hf * 8;
                redS[r_l * 4 + wn] = s;
                redM[r_l * 4 + wn] = mx;
            }
        }
    __syncthreads();
    if (tid < 128) {
        float s = redS[tid * 4] + redS[tid * 4 + 1] + redS[tid * 4 + 2] + redS[tid * 4 + 3];
        float mx = fmaxf(fmaxf(redM[tid * 4], redM[tid * 4 + 1]),
                         fmaxf(redM[tid * 4 + 2], redM[tid * 4 + 3]));
        g_avg_sp[m0 + tid] = s * (1.f / 256.f);
        g_max_sp[m0 + tid] = mx;
    }
}

// ============================================================================
// spstats: 7x7 spatial conv (smem-staged 10-row neighborhood) + sigmoid gate
// + per-(b,c) sum/max partials. grid 200, block 256.
// ============================================================================
__global__ void spstats(const float* __restrict__ sa_w) {
    __shared__ float sw[98];
    __shared__ float avgS[800], maxS[800];
    __shared__ float gate_s[256];
    __shared__ float ss[512], mm_[512];
    const int tid = threadIdx.x;
    if (tid < 98) sw[tid] = sa_w[tid];
    const int m0 = blockIdx.x * 256;
    const int bb = m0 / HWQ;
    const int s0 = m0 % HWQ;
    const int h0 = s0 / 80;
    const int baseP = (h0 - 3) * 80;
    for (int t = tid; t < 800; t += 256) {
        int p = baseP + t;
        float a = 0.f, mx = 0.f;
        if ((unsigned)p < (unsigned)HWQ) {
            int mi = bb * HWQ + p;
            a = g_avg_sp[mi];
            mx = g_max_sp[mi];
        }
        avgS[t] = a;
        maxS[t] = mx;
    }
    __syncthreads();
    {
        int s = s0 + tid;
        int h = s / 80, w = s % 80;
        float acc = 0.f;
#pragma unroll
        for (int ky = 0; ky < 7; ky++) {
            int y = h + ky - 3;
            if ((unsigned)y < 80u) {
                int lrow = (y - (h0 - 3)) * 80;
#pragma unroll
                for (int kx = 0; kx < 7; kx++) {
                    int xx = w + kx - 3;
                    if ((unsigned)xx < 80u)
                        acc += avgS[lrow + xx] * sw[ky * 7 + kx]
                             + maxS[lrow + xx] * sw[49 + ky * 7 + kx];
                }
            }
        }
        float g = 1.f / (1.f + expf(-acc));
        g_gate[m0 + tid] = g;
        gate_s[tid] = g;
    }
    __syncthreads();
    const int c2 = tid & 127;
    const int rp = tid >> 7;
    const __half2* fh = (const __half2*)g_fused;
    float s0f = 0.f, s1f = 0.f, x0 = 0.f, x1 = 0.f;
#pragma unroll 4
    for (int r = rp; r < 256; r += 2) {
        float gg = gate_s[r];
        float2 f = __half22float2(fh[(long)(m0 + r) * 128 + c2]);
        float a = gg * f.x, b = gg * f.y;
        s0f += a; s1f += b;
        x0 = fmaxf(x0, a); x1 = fmaxf(x1, b);
    }
    ss[(2 * c2 + 0) * 2 + rp] = s0f;
    ss[(2 * c2 + 1) * 2 + rp] = s1f;
    mm_[(2 * c2 + 0) * 2 + rp] = x0;
    mm_[(2 * c2 + 1) * 2 + rp] = x1;
    __syncthreads();
    const int seg = (m0 % HWQ) >> 8;
    float s = ss[tid * 2] + ss[tid * 2 + 1];
    float mx = fmaxf(mm_[tid * 2], mm_[tid * 2 + 1]);
    g_chsum_part[(seg * BQ + bb) * 256 + tid] = s;
    g_chmax_part[(seg * BQ + bb) * 256 + tid] = mx;
}

// ============================================================================
// GEMM2 (fp16 HMMA k16): 512 thr, full-K gated A resident (128 x 264h).
// Channel-MLP (chmap) computed per-CTA in the prologue (replaces chmlp
// kernel) while B(0)/B(1) cp.asyncs are in flight; uses the A region as
// scratch. 4 n-blocks of 256, k-chunk 64, 3-stage B ring (distance-2).
// Warp tile 32x64. Epilogue: bias+relu -> iDWT (shfl) -> +identity -> out.
// smem: A@0(67584) B 3x36864 @67584 bias@178176(4096) cmap@182272(1024)
//       gate@183296(512)  total 183808
// ============================================================================
#define G2_SMEM 183808
__global__ __launch_bounds__(512) void gemm2(const float* __restrict__ x,
                                             const float* __restrict__ ca_w1,
                                             const float* __restrict__ ca_w2,
                                             float* __restrict__ out) {
    extern __shared__ char smem[];
    const uint32_t sb = smem_u32(smem);
    const int tid = threadIdx.x;
    const int lane = tid & 31, warp = tid >> 5;
    const int wm = warp & 3, wn = warp >> 2;
    const int m0 = blockIdx.x * 128;
    const int bb = m0 / HWQ;
    const int hw0 = m0 % HWQ;

    float* biasS = (float*)(smem + 178176);
    float* cmapS = (float*)(smem + 182272);
    float* gateS = (float*)(smem + 183296);
    if (tid < 256) ((float4*)biasS)[tid] = ((const float4*)g_bias2p)[tid];
    if (tid < 32) ((float4*)gateS)[tid] = ((const float4*)(g_gate + m0))[tid];

    // ---- B cp.async setup
    const int rowB = tid >> 1;
    const int colH = (tid & 1) * 32;
    const uint32_t bDstOff = (uint32_t)(rowB * 144 + colH * 2);

    // prologue: B(0)->s0, B(1)->s1 in flight (independent of A fill / chmap)
    {
        uint32_t bD = sb + 67584u + bDstOff;
        const __half* bS = g_W2h + rowB * 256 + colH;
        cpa16(bD, bS); cpa16(bD + 16, bS + 8); cpa16(bD + 32, bS + 16); cpa16(bD + 48, bS + 24);
        CP_COMMIT;
        bD = sb + 67584u + 36864u + bDstOff;
        bS = g_W2h + rowB * 256 + 64 + colH;
        cpa16(bD, bS); cpa16(bD + 16, bS + 8); cpa16(bD + 32, bS + 16); cpa16(bD + 48, bS + 24);
        CP_COMMIT;
    }

    // ---- chmap (channel MLP) computed in-CTA; scratch in A region ----
    {
        float* sA = (float*)smem;            // 256 floats
        float* sM = (float*)(smem + 1024);   // 256 floats
        float* sH = (float*)(smem + 2048);   // 32 floats
        if (tid < 256) {
            float s = 0.f, mx = 0.f;
#pragma unroll
            for (int seg = 0; seg < NSEG; seg++) {
                s += g_chsum_part[(seg * BQ + bb) * 256 + tid];
                mx = fmaxf(mx, g_chmax_part[(seg * BQ + bb) * 256 + tid]);
            }
            sA[tid] = s * (1.f / 6400.f);
            sM[tid] = mx;
        }
        __syncthreads();
        if (tid < 256) {
            int wq = tid >> 5, ln = tid & 31;
#pragma unroll
            for (int it = 0; it < 4; it++) {
                int t = wq * 4 + it;          // 0..31
                int u = t & 15, which = t >> 4;
                const float* vec = which ? sM : sA;
                float d = 0.f;
                for (int cc = ln; cc < 256; cc += 32) d += ca_w1[u * 256 + cc] * vec[cc];
#pragma unroll
                for (int off = 16; off; off >>= 1) d += __shfl_xor_sync(0xffffffffu, d, off);
                if (ln == 0) sH[t] = fmaxf(d, 0.f);
            }
        }
        __syncthreads();
        if (tid < 256) {
            float o = 0.f;
#pragma unroll
            for (int u = 0; u < 16; u++) o += ca_w2[tid * 16 + u] * (sH[u] + sH[16 + u]);
            cmapS[tid] = 1.f / (1.f + expf(-o));
        }
        __syncthreads();
    }

    // ---- fill full-K A tile: fused(fp16) * gate * cmap -> fp16 (row pad 264h)
    {
        const int kqA = tid & 63;            // channels kqA*4 .. +3
        const int ml0 = tid >> 6;
        const __half2* fh = (const __half2*)g_fused;
#pragma unroll
        for (int i = 0; i < 16; ++i) {
            int m_l = ml0 + i * 8;
            float2 f01 = __half22float2(fh[(long)(m0 + m_l) * 128 + kqA * 2]);
            float2 f23 = __half22float2(fh[(long)(m0 + m_l) * 128 + kqA * 2 + 1]);
            float gm = gateS[m_l];
            f01.x *= gm * cmapS[kqA * 4 + 0];
            f01.y *= gm * cmapS[kqA * 4 + 1];
            f23.x *= gm * cmapS[kqA * 4 + 2];
            f23.y *= gm * cmapS[kqA * 4 + 3];
            *(__half2*)(smem + m_l * 528 + kqA * 8)     = __floats2half2_rn(f01.x, f01.y);
            *(__half2*)(smem + m_l * 528 + kqA * 8 + 4) = __floats2half2_rn(f23.x, f23.y);
        }
    }

    const uint32_t aLd = sb + (uint32_t)((wm * 32 + (lane & 15)) * 528 + (lane >> 4) * 16);
    const uint32_t bLd = sb + 67584u + (uint32_t)((wn * 64 + (lane & 15)) * 144 + (lane >> 4) * 16);

    float acc[2][8][4];
#pragma unroll
    for (int a = 0; a < 2; a++)
#pragma unroll
        for (int b = 0; b < 8; b++)
#pragma unroll
            for (int c = 0; c < 4; c++) acc[a][b][c] = 0.f;

    for (int it = 0; it < 16; ++it) {    // it = nb*4 + kc
        const int kc = it & 3;
        if (it < 15) { CP_WAIT1; } else { CP_WAIT0; }
        __syncthreads();                 // B(it) (+ A fill at it=0) visible
        if (it < 14) {                   // B(it+2) -> stage (it+2)%3
            int nn = it + 2;
            uint32_t bD = sb + 67584u + (uint32_t)((nn % 3) * 36864) + bDstOff;
            const __half* bS = g_W2h + ((nn >> 2) * 256 + rowB) * 256 + (nn & 3) * 64 + colH;
            cpa16(bD, bS); cpa16(bD + 16, bS + 8); cpa16(bD + 32, bS + 16); cpa16(bD + 48, bS + 24);
            CP_COMMIT;
        }
        const uint32_t aB = aLd + (uint32_t)(kc * 128);   // kc * 64 halves
        const uint32_t bB = bLd + (uint32_t)((it % 3) * 36864);
#pragma unroll
        for (int kk = 0; kk < 4; ++kk) {
            uint32_t af[2][4], bf[4][4];
            ldsm4(af[0], aB + kk * 32);
            ldsm4(af[1], aB + kk * 32 + 16 * 528);
#pragma unroll
            for (int i = 0; i < 4; ++i) ldsm4(bf[i], bB + kk * 32 + i * 16 * 144);
#pragma unroll
            for (int ms = 0; ms < 2; ++ms)
#pragma unroll
                for (int i = 0; i < 4; ++i) {
                    mma16(acc[ms][2 * i + 0], af[ms], bf[i][0], bf[i][2]);
                    mma16(acc[ms][2 * i + 1], af[ms], bf[i][1], bf[i][3]);
                }
        }
        if (kc == 3) {
            // ---- epilogue for n-block nb: bias+relu -> iDWT -> +identity
            const int nb = it >> 2;
#pragma unroll
            for (int ms = 0; ms < 2; ++ms) {
#pragma unroll
                for (int hf = 0; hf < 2; ++hf) {
                    int m_l = wm * 32 + ms * 16 + (lane >> 2) + hf * 8;
                    int hw = hw0 + m_l;
                    int h = hw / 80, w = hw - h * 80;
#pragma unroll
                    for (int ns = 0; ns < 8; ++ns) {
                        int jc = nb * 256 + wn * 64 + ns * 8 + (lane & 3) * 2;
                        float v0 = fmaxf(acc[ms][ns][hf * 2 + 0] + biasS[jc], 0.f);
                        float v1 = fmaxf(acc[ms][ns][hf * 2 + 1] + biasS[jc + 1], 0.f);
                        float p = v0 + v1;
                        float r = v0 - v1;
                        float op = __shfl_xor_sync(0xffffffffu, p, 1);
                        float orr = __shfl_xor_sync(0xffffffffu, r, 1);
                        float e0, e1;
                        if (lane & 1) {         // bottom row: oc, od
                            e0 = 0.5f * (orr + r);
                            e1 = 0.5f * (orr - r);
                        } else {                // top row: oa, ob
                            e0 = 0.5f * (p + op);
                            e1 = 0.5f * (p - op);
                        }
                        int cp = jc >> 2;
                        long base = (((long)bb * 256 + cp) * 160 + 2 * h + (lane & 1)) * 160 + 2 * w;
                        float2 xi = *(const float2*)(x + base);
                        *(float2*)(out + base) = make_float2(e0 + xi.x, e1 + xi.y);
                    }
                }
            }
#pragma unroll
            for (int a = 0; a < 2; a++)
#pragma unroll
                for (int b = 0; b < 8; b++)
#pragma unroll
                    for (int c = 0; c < 4; c++) acc[a][b][c] = 0.f;
        }
    }
}

// ---------------- host launch ---------------------------------------------
extern "C" void kernel_launch(void* const* d_in, const int* in_sizes, int n_in,
                              void* d_out, int out_size) {
    (void)in_sizes; (void)n_in; (void)out_size;
    const float* x        = (const float*)d_in[0];
    const float* fusion_w = (const float*)d_in[1];
    const float* fusion_b = (const float*)d_in[2];
    const float* bn1_g    = (const float*)d_in[3];
    const float* bn1_b    = (const float*)d_in[4];
    const float* bn1_m    = (const float*)d_in[5];
    const float* bn1_v    = (const float*)d_in[6];
    const float* sa_w     = (const float*)d_in[7];
    const float* ca_w1    = (const float*)d_in[8];
    const float* ca_w2    = (const float*)d_in[9];
    const float* proj_w   = (const float*)d_in[10];
    const float* proj_b   = (const float*)d_in[11];
    const float* bn2_g    = (const float*)d_in[12];
    const float* bn2_b    = (const float*)d_in[13];
    const float* bn2_m    = (const float*)d_in[14];
    const float* bn2_v    = (const float*)d_in[15];
    float* out = (float*)d_out;

    cudaFuncSetAttribute(gemm1, cudaFuncAttributeMaxDynamicSharedMemorySize, G1_SMEM);
    cudaFuncSetAttribute(gemm2, cudaFuncAttributeMaxDynamicSharedMemorySize, G2_SMEM);

    // gemm2 is now the 4th launch -> next round's ncu capture shows it.
    prep<<<(2 * K1 * N1) / 256, 256>>>(fusion_w, fusion_b, bn1_g, bn1_b, bn1_m, bn1_v,
                                       proj_w, proj_b, bn2_g, bn2_b, bn2_m, bn2_v);
    gemm1<<<MTOT / 128, 512, G1_SMEM>>>(x);
    spstats<<<MTOT / 256, 256>>>(sa_w);
    gemm2<<<MTOT / 128, 512, G2_SMEM>>>(x, ca_w1, ca_w2, out);
}

// round 14
// speedup vs baseline: 1.0188x; 1.0188x over previous
#include <cuda_runtime.h>
#include <cuda_fp16.h>
#include <cstdint>

// ---------------- problem constants ----------------
#define BQ    8
#define HWQ   6400          // 80*80
#define MTOT  51200         // 8*6400
#define K1    1024
#define N1    256
#define K2    256
#define N2    1024
#define NSEG  25            // 6400 / 256

// ---------------- scratch (device globals) --------
__device__ __align__(16) __half g_W1h[N1 * K1];      // [n][k] fp16 (DWT+BN1 folded)
__device__ __align__(16) float  g_bias1[N1];
__device__ __align__(16) __half g_W2h[N2 * K2];      // [j][k] fp16, j = c'*4+g (permuted)
__device__ __align__(16) float  g_bias2p[N2];
__device__ __align__(16) __half g_fused[(long)MTOT * 256];   // fp16 (26 MB)
__device__ __align__(16) float  g_avg_sp[MTOT];
__device__ __align__(16) float  g_max_sp[MTOT];
__device__ __align__(16) float  g_gate[MTOT];
__device__ __align__(16) float  g_chsum_part[NSEG * BQ * 256];
__device__ __align__(16) float  g_chmax_part[NSEG * BQ * 256];

// ---------------- PTX helpers ----------------------
__device__ __forceinline__ uint32_t smem_u32(const void* p) {
    uint32_t a;
    asm("{ .reg .u64 t; cvta.to.shared.u64 t, %1; cvt.u32.u64 %0, t; }" : "=r"(a) : "l"(p));
    return a;
}
__device__ __forceinline__ void ldsm4(uint32_t* r, uint32_t addr) {
    asm volatile("ldmatrix.sync.aligned.m8n8.x4.shared.b16 {%0,%1,%2,%3}, [%4];"
                 : "=r"(r[0]), "=r"(r[1]), "=r"(r[2]), "=r"(r[3]) : "r"(addr));
}
__device__ __forceinline__ void ldsm4t(uint32_t* r, uint32_t addr) {
    asm volatile("ldmatrix.sync.aligned.m8n8.x4.trans.shared.b16 {%0,%1,%2,%3}, [%4];"
                 : "=r"(r[0]), "=r"(r[1]), "=r"(r[2]), "=r"(r[3]) : "r"(addr));
}
__device__ __forceinline__ void mma16(float* d, const uint32_t* a, uint32_t b0, uint32_t b1) {
    asm volatile(
        "mma.sync.aligned.m16n8k16.row.col.f32.f16.f16.f32 "
        "{%0,%1,%2,%3}, {%4,%5,%6,%7}, {%8,%9}, {%0,%1,%2,%3};"
        : "+f"(d[0]), "+f"(d[1]), "+f"(d[2]), "+f"(d[3])
        : "r"(a[0]), "r"(a[1]), "r"(a[2]), "r"(a[3]), "r"(b0), "r"(b1));
}
__device__ __forceinline__ void cpa16(uint32_t dst, const void* src) {
    asm volatile("cp.async.cg.shared.global [%0], [%1], 16;" :: "r"(dst), "l"(src));
}
#define CP_COMMIT asm volatile("cp.async.commit_group;" ::: "memory")
#define CP_WAIT1  asm volatile("cp.async.wait_group 1;" ::: "memory")
#define CP_WAIT0  asm volatile("cp.async.wait_group 0;" ::: "memory")

// ---------------- prep: fold DWT+BN1 into W1; BN2+permute into W2 ---------
__global__ void prep(const float* __restrict__ fw, const float* __restrict__ fb,
                     const float* __restrict__ g1, const float* __restrict__ b1,
                     const float* __restrict__ m1, const float* __restrict__ v1,
                     const float* __restrict__ pw, const float* __restrict__ pb,
                     const float* __restrict__ g2, const float* __restrict__ b2,
                     const float* __restrict__ m2, const float* __restrict__ v2) {
    int idx = blockIdx.x * blockDim.x + threadIdx.x;
    if (idx < K1 * N1) {
        int o = idx & 255;
        int k = idx >> 8;            // k = c*4 + q, q = 2*dy + dx
        int c = k >> 2, q = k & 3;
        float inv = g1[o] * rsqrtf(v1[o] + 1e-5f);
        float slh = (q < 2) ? 1.f : -1.f;
        float shl = ((q & 1) == 0) ? 1.f : -1.f;
        float shh = slh * shl;
        float val = fw[o * 1024 + c]
                  + slh * fw[o * 1024 + 256 + c]
                  + shl * fw[o * 1024 + 512 + c]
                  + shh * fw[o * 1024 + 768 + c];
        g_W1h[o * 1024 + k] = __float2half_rn(0.5f * inv * val);
        if (k == 0) g_bias1[o] = fb[o] * inv + b1[o] - m1[o] * inv;
    } else {
        int idx2 = idx - K1 * N1;
        int j = idx2 & 1023;          // j = c'*4 + g
        int k = idx2 >> 10;
        int o = (j & 3) * 256 + (j >> 2);
        float inv = g2[o] * rsqrtf(v2[o] + 1e-5f);
        g_W2h[j * 256 + k] = __float2half_rn(pw[o * 256 + k] * inv);
        if (k == 0) g_bias2p[j] = pb[o] * inv + b2[o] - m2[o] * inv;
    }
}

// ============================================================================
// GEMM1 (fp16 HMMA k16): CTA 128m x 256n, 512 thr (16 warps 4m x 4n, warp
// tile 32x64), k-chunk 64 (16 chunks). A stored TRANSPOSED [k][m] (272B rows)
// -> conflict-free STS; A frags via ldmatrix.x4.trans. 3-stage A STS ring +
// 3-stage B cp.async ring, distance-2 waits.
// smem: A 3x17408 @0; B 3x36864 @52224; bias@162816(1024) redS@163840(2048)
//       redM@165888(2048)  total 167936
// ============================================================================
#define G1_SMEM 167936
__global__ __launch_bounds__(512) void gemm1(const float* __restrict__ x) {
    extern __shared__ char smem[];
    const uint32_t sb = smem_u32(smem);
    const int tid = threadIdx.x;
    const int lane = tid & 31, warp = tid >> 5;
    const int wm = warp & 3, wn = warp >> 2;
    const int m0 = blockIdx.x * 128;
    const int bb = m0 / HWQ;
    const int hw0 = m0 % HWQ;

    if (tid < 64) ((float4*)(smem + 162816))[tid] = ((const float4*)g_bias1)[tid];

    // ---- A gather setup (chunk ch covers channels ch*16 .. ch*16+15)
    const int cA = tid >> 7;
    const int dyA = (tid >> 6) & 1;
    const int mlA = (tid & 63) * 2;
    const int hwA = hw0 + mlA;
    const int hA = hwA / 80, wA = hwA - hA * 80;
    const float* aBase = x + (long)bb * 256 * 25600 + cA * 25600 + (2 * hA + dyA) * 160 + 2 * wA;
    const int aRowOff = (cA * 4 + dyA * 2) * 272 + mlA * 2;   // bytes

    // ---- B cp.async setup: 256 rows x 64 halves (128B) per chunk
    const int rowB = tid >> 1;
    const int colH = (tid & 1) * 32;
    const __half* bSrcBase = g_W1h + rowB * 1024 + colH;
    const uint32_t bDstOff = (uint32_t)(rowB * 144 + colH * 2);

    // ---- ldsm lane bases
    const uint32_t aLd = sb
        + (uint32_t)(((lane & 7) + ((lane >> 4) << 3)) * 272
                     + (wm * 32 + ((lane >> 3) & 1) * 8) * 2);
    const uint32_t bLd = sb + 52224u + (uint32_t)((wn * 64 + (lane & 15)) * 144 + (lane >> 4) * 16);

    float acc[2][8][4];
#pragma unroll
    for (int a = 0; a < 2; a++)
#pragma unroll
        for (int b = 0; b < 8; b++)
#pragma unroll
            for (int c = 0; c < 4; c++) acc[a][b][c] = 0.f;

    // ---- prologue
    float4 aP[4];
#pragma unroll
    for (int i = 0; i < 4; ++i) aP[i] = *(const float4*)(aBase + i * 4 * 25600);
    {
        char* aSt = smem + aRowOff;
#pragma unroll
        for (int i = 0; i < 4; ++i) {
            *(__half2*)(aSt + i * 16 * 272)       = __floats2half2_rn(aP[i].x, aP[i].z);
            *(__half2*)(aSt + i * 16 * 272 + 272) = __floats2half2_rn(aP[i].y, aP[i].w);
        }
    }
#pragma unroll
    for (int i = 0; i < 4; ++i) aP[i] = *(const float4*)(aBase + 409600 + i * 4 * 25600);
    {
        uint32_t bD = sb + 52224u + bDstOff;
        const __half* bS = bSrcBase;
        cpa16(bD, bS); cpa16(bD + 16, bS + 8); cpa16(bD + 32, bS + 16); cpa16(bD + 48, bS + 24);
        CP_COMMIT;
        bD = sb + 52224u + 36864u + bDstOff;
        bS = bSrcBase + 64;
        cpa16(bD, bS); cpa16(bD + 16, bS + 8); cpa16(bD + 32, bS + 16); cpa16(bD + 48, bS + 24);
        CP_COMMIT;
    }

    for (int it = 0; it < 16; ++it) {
        if (it < 15) { CP_WAIT1; } else { CP_WAIT0; }
        __syncthreads();
        if (it < 15) {
            char* aSt = smem + ((it + 1) % 3) * 17408 + aRowOff;
#pragma unroll
            for (int i = 0; i < 4; ++i) {
                *(__half2*)(aSt + i * 16 * 272)       = __floats2half2_rn(aP[i].x, aP[i].z);
                *(__half2*)(aSt + i * 16 * 272 + 272) = __floats2half2_rn(aP[i].y, aP[i].w);
            }
        }
        if (it < 14) {
            uint32_t bD = sb + 52224u + (uint32_t)(((it + 2) % 3) * 36864) + bDstOff;
            const __half* bS = bSrcBase + (it + 2) * 64;
            cpa16(bD, bS); cpa16(bD + 16, bS + 8); cpa16(bD + 32, bS + 16); cpa16(bD + 48, bS + 24);
            CP_COMMIT;
#pragma unroll
            for (int i = 0; i < 4; ++i)
                aP[i] = *(const float4*)(aBase + (long)(it + 2) * 409600 + i * 4 * 25600);
        }
        const uint32_t aB = aLd + (uint32_t)((it % 3) * 17408);
        const uint32_t bB = bLd + (uint32_t)((it % 3) * 36864);
#pragma unroll
        for (int kk = 0; kk < 4; ++kk) {
            uint32_t af[2][4], bf[4][4];
            ldsm4t(af[0], aB + kk * 16 * 272);
            ldsm4t(af[1], aB + kk * 16 * 272 + 32);
#pragma unroll
            for (int i = 0; i < 4; ++i) ldsm4(bf[i], bB + kk * 32 + i * 16 * 144);
#pragma unroll
            for (int ms = 0; ms < 2; ++ms)
#pragma unroll
                for (int i = 0; i < 4; ++i) {
                    mma16(acc[ms][2 * i + 0], af[ms], bf[i][0], bf[i][2]);
                    mma16(acc[ms][2 * i + 1], af[ms], bf[i][1], bf[i][3]);
                }
        }
    }

    // ---- epilogue: bias+relu -> g_fused (fp16); full-row sum/max
    const float* biasS = (const float*)(smem + 162816);
    float* redS = (float*)(smem + 163840);
    float* redM = (float*)(smem + 165888);
    __half2* fh2 = (__half2*)g_fused;
    float rs[2][2] = {{0.f, 0.f}, {0.f, 0.f}};
    float rm[2][2] = {{0.f, 0.f}, {0.f, 0.f}};
#pragma unroll
    for (int ms = 0; ms < 2; ++ms) {
        int row0 = m0 + wm * 32 + ms * 16 + (lane >> 2);
#pragma unroll
        for (int ns = 0; ns < 8; ++ns) {
            int col = wn * 64 + ns * 8 + (lane & 3) * 2;
            float b0 = biasS[col], b1 = biasS[col + 1];
            float v0 = fmaxf(acc[ms][ns][0] + b0, 0.f);
            float v1 = fmaxf(acc[ms][ns][1] + b1, 0.f);
            fh2[(long)row0 * 128 + (col >> 1)] = __floats2half2_rn(v0, v1);
            rs[ms][0] += v0 + v1;
            rm[ms][0] = fmaxf(rm[ms][0], fmaxf(v0, v1));
            float v2 = fmaxf(acc[ms][ns][2] + b0, 0.f);
            float v3 = fmaxf(acc[ms][ns][3] + b1, 0.f);
            fh2[(long)(row0 + 8) * 128 + (col >> 1)] = __floats2half2_rn(v2, v3);
            rs[ms][1] += v2 + v3;
            rm[ms][1] = fmaxf(rm[ms][1], fmaxf(v2, v3));
        }
    }
#pragma unroll
    for (int ms = 0; ms < 2; ++ms)
#pragma unroll
        for (int hf = 0; hf < 2; ++hf) {
            float s = rs[ms][hf], mx = rm[ms][hf];
            s += __shfl_xor_sync(0xffffffffu, s, 1);
            s += __shfl_xor_sync(0xffffffffu, s, 2);
            mx = fmaxf(mx, __shfl_xor_sync(0xffffffffu, mx, 1));
            mx = fmaxf(mx, __shfl_xor_sync(0xffffffffu, mx, 2));
            if ((lane & 3) == 0) {
                int r_l = wm * 32 + ms * 16 + (lane >> 2) + hf * 8;
                redS[r_l * 4 + wn] = s;
                redM[r_l * 4 + wn] = mx;
            }
        }
    __syncthreads();
    if (tid < 128) {
        float s = redS[tid * 4] + redS[tid * 4 + 1] + redS[tid * 4 + 2] + redS[tid * 4 + 3];
        float mx = fmaxf(fmaxf(redM[tid * 4], redM[tid * 4 + 1]),
                         fmaxf(redM[tid * 4 + 2], redM[tid * 4 + 3]));
        g_avg_sp[m0 + tid] = s * (1.f / 256.f);
        g_max_sp[m0 + tid] = mx;
    }
}

// ============================================================================
// spstats: 7x7 spatial conv (smem-staged 10-row neighborhood) + sigmoid gate
// + per-(b,c) sum/max partials. grid 200, block 256.
// ============================================================================
__global__ void spstats(const float* __restrict__ sa_w) {
    __shared__ float sw[98];
    __shared__ float avgS[800], maxS[800];
    __shared__ float gate_s[256];
    __shared__ float ss[512], mm_[512];
    const int tid = threadIdx.x;
    if (tid < 98) sw[tid] = sa_w[tid];
    const int m0 = blockIdx.x * 256;
    const int bb = m0 / HWQ;
    const int s0 = m0 % HWQ;
    const int h0 = s0 / 80;
    const int baseP = (h0 - 3) * 80;
    for (int t = tid; t < 800; t += 256) {
        int p = baseP + t;
        float a = 0.f, mx = 0.f;
        if ((unsigned)p < (unsigned)HWQ) {
            int mi = bb * HWQ + p;
            a = g_avg_sp[mi];
            mx = g_max_sp[mi];
        }
        avgS[t] = a;
        maxS[t] = mx;
    }
    __syncthreads();
    {
        int s = s0 + tid;
        int h = s / 80, w = s % 80;
        float acc = 0.f;
#pragma unroll
        for (int ky = 0; ky < 7; ky++) {
            int y = h + ky - 3;
            if ((unsigned)y < 80u) {
                int lrow = (y - (h0 - 3)) * 80;
#pragma unroll
                for (int kx = 0; kx < 7; kx++) {
                    int xx = w + kx - 3;
                    if ((unsigned)xx < 80u)
                        acc += avgS[lrow + xx] * sw[ky * 7 + kx]
                             + maxS[lrow + xx] * sw[49 + ky * 7 + kx];
                }
            }
        }
        float g = 1.f / (1.f + expf(-acc));
        g_gate[m0 + tid] = g;
        gate_s[tid] = g;
    }
    __syncthreads();
    const int c2 = tid & 127;
    const int rp = tid >> 7;
    const __half2* fh = (const __half2*)g_fused;
    float s0f = 0.f, s1f = 0.f, x0 = 0.f, x1 = 0.f;
#pragma unroll 4
    for (int r = rp; r < 256; r += 2) {
        float gg = gate_s[r];
        float2 f = __half22float2(fh[(long)(m0 + r) * 128 + c2]);
        float a = gg * f.x, b = gg * f.y;
        s0f += a; s1f += b;
        x0 = fmaxf(x0, a); x1 = fmaxf(x1, b);
    }
    ss[(2 * c2 + 0) * 2 + rp] = s0f;
    ss[(2 * c2 + 1) * 2 + rp] = s1f;
    mm_[(2 * c2 + 0) * 2 + rp] = x0;
    mm_[(2 * c2 + 1) * 2 + rp] = x1;
    __syncthreads();
    const int seg = (m0 % HWQ) >> 8;
    float s = ss[tid * 2] + ss[tid * 2 + 1];
    float mx = fmaxf(mm_[tid * 2], mm_[tid * 2 + 1]);
    g_chsum_part[(seg * BQ + bb) * 256 + tid] = s;
    g_chmax_part[(seg * BQ + bb) * 256 + tid] = mx;
}

// ============================================================================
// GEMM2 (fp16 HMMA k16): 512 thr, full-K gated A resident (128 x 264h).
// chmap computed per-CTA in prologue. 4 n-blocks of 256, k-chunk 64,
// 3-stage B ring (distance-2). Warp tile 32x64.
// Staged epilogue: per n-block, barrier (ends all reads of stage it%3), then
// 4 quarter-passes: STS accs into fp32 [64j'][128m] stage -> barrier ->
// per-warp channel iDWT (float4 LDS) + coalesced float4 identity + stores.
// smem: A@0(67584) B 3x36864 @67584 bias@178176(4096) cmap@182272(1024)
//       gate@183296(512)  total 183808
// ============================================================================
#define G2_SMEM 183808
__global__ __launch_bounds__(512) void gemm2(const float* __restrict__ x,
                                             const float* __restrict__ ca_w1,
                                             const float* __restrict__ ca_w2,
                                             float* __restrict__ out) {
    extern __shared__ char smem[];
    const uint32_t sb = smem_u32(smem);
    const int tid = threadIdx.x;
    const int lane = tid & 31, warp = tid >> 5;
    const int wm = warp & 3, wn = warp >> 2;
    const int m0 = blockIdx.x * 128;
    const int bb = m0 / HWQ;
    const int hw0 = m0 % HWQ;

    float* biasS = (float*)(smem + 178176);
    float* cmapS = (float*)(smem + 182272);
    float* gateS = (float*)(smem + 183296);
    if (tid < 256) ((float4*)biasS)[tid] = ((const float4*)g_bias2p)[tid];
    if (tid < 32) ((float4*)gateS)[tid] = ((const float4*)(g_gate + m0))[tid];

    // ---- write-phase constants (epilogue): warp -> channel slot, lane -> 4 px
    const int sWn = warp >> 2, sLq = warp & 3;
    const int hwE = hw0 + lane * 4;
    const int hE = hwE / 80, wE = hwE - hE * 80;
    const long rowT = ((long)(2 * hE)) * 160 + 2 * wE;

    // ---- B cp.async setup
    const int rowB = tid >> 1;
    const int colH = (tid & 1) * 32;
    const uint32_t bDstOff = (uint32_t)(rowB * 144 + colH * 2);

    // prologue: B(0)->s0, B(1)->s1 in flight
    {
        uint32_t bD = sb + 67584u + bDstOff;
        const __half* bS = g_W2h + rowB * 256 + colH;
        cpa16(bD, bS); cpa16(bD + 16, bS + 8); cpa16(bD + 32, bS + 16); cpa16(bD + 48, bS + 24);
        CP_COMMIT;
        bD = sb + 67584u + 36864u + bDstOff;
        bS = g_W2h + rowB * 256 + 64 + colH;
        cpa16(bD, bS); cpa16(bD + 16, bS + 8); cpa16(bD + 32, bS + 16); cpa16(bD + 48, bS + 24);
        CP_COMMIT;
    }

    // ---- chmap (channel MLP) computed in-CTA; scratch in A region ----
    {
        float* sA = (float*)smem;            // 256 floats
        float* sM = (float*)(smem + 1024);   // 256 floats
        float* sH = (float*)(smem + 2048);   // 32 floats
        if (tid < 256) {
            float s = 0.f, mx = 0.f;
#pragma unroll
            for (int seg = 0; seg < NSEG; seg++) {
                s += g_chsum_part[(seg * BQ + bb) * 256 + tid];
                mx = fmaxf(mx, g_chmax_part[(seg * BQ + bb) * 256 + tid]);
            }
            sA[tid] = s * (1.f / 6400.f);
            sM[tid] = mx;
        }
        __syncthreads();
        if (tid < 256) {
            int wq = tid >> 5, ln = tid & 31;
#pragma unroll
            for (int it = 0; it < 4; it++) {
                int t = wq * 4 + it;
                int u = t & 15, which = t >> 4;
                const float* vec = which ? sM : sA;
                float d = 0.f;
                for (int cc = ln; cc < 256; cc += 32) d += ca_w1[u * 256 + cc] * vec[cc];
#pragma unroll
                for (int off = 16; off; off >>= 1) d += __shfl_xor_sync(0xffffffffu, d, off);
                if (ln == 0) sH[t] = fmaxf(d, 0.f);
            }
        }
        __syncthreads();
        if (tid < 256) {
            float o = 0.f;
#pragma unroll
            for (int u = 0; u < 16; u++) o += ca_w2[tid * 16 + u] * (sH[u] + sH[16 + u]);
            cmapS[tid] = 1.f / (1.f + expf(-o));
        }
        __syncthreads();
    }

    // ---- fill full-K A tile: fused(fp16) * gate * cmap -> fp16 (row pad 264h)
    {
        const int kqA = tid & 63;
        const int ml0 = tid >> 6;
        const __half2* fh = (const __half2*)g_fused;
#pragma unroll
        for (int i = 0; i < 16; ++i) {
            int m_l = ml0 + i * 8;
            float2 f01 = __half22float2(fh[(long)(m0 + m_l) * 128 + kqA * 2]);
            float2 f23 = __half22float2(fh[(long)(m0 + m_l) * 128 + kqA * 2 + 1]);
            float gm = gateS[m_l];
            f01.x *= gm * cmapS[kqA * 4 + 0];
            f01.y *= gm * cmapS[kqA * 4 + 1];
            f23.x *= gm * cmapS[kqA * 4 + 2];
            f23.y *= gm * cmapS[kqA * 4 + 3];
            *(__half2*)(smem + m_l * 528 + kqA * 8)     = __floats2half2_rn(f01.x, f01.y);
            *(__half2*)(smem + m_l * 528 + kqA * 8 + 4) = __floats2half2_rn(f23.x, f23.y);
        }
    }

    const uint32_t aLd = sb + (uint32_t)((wm * 32 + (lane & 15)) * 528 + (lane >> 4) * 16);
    const uint32_t bLd = sb + 67584u + (uint32_t)((wn * 64 + (lane & 15)) * 144 + (lane >> 4) * 16);

    float acc[2][8][4];
#pragma unroll
    for (int a = 0; a < 2; a++)
#pragma unroll
        for (int b = 0; b < 8; b++)
#pragma unroll
            for (int c = 0; c < 4; c++) acc[a][b][c] = 0.f;

    for (int it = 0; it < 16; ++it) {    // it = nb*4 + kc
        const int kc = it & 3;
        if (it < 15) { CP_WAIT1; } else { CP_WAIT0; }
        __syncthreads();                 // B(it) (+ A fill at it=0) visible
        if (it < 14) {                   // B(it+2) -> stage (it+2)%3
            int nn = it + 2;
            uint32_t bD = sb + 67584u + (uint32_t)((nn % 3) * 36864) + bDstOff;
            const __half* bS = g_W2h + ((nn >> 2) * 256 + rowB) * 256 + (nn & 3) * 64 + colH;
            cpa16(bD, bS); cpa16(bD + 16, bS + 8); cpa16(bD + 32, bS + 16); cpa16(bD + 48, bS + 24);
            CP_COMMIT;
        }
        const uint32_t aB = aLd + (uint32_t)(kc * 128);   // kc * 64 halves
        const uint32_t bB = bLd + (uint32_t)((it % 3) * 36864);
#pragma unroll
        for (int kk = 0; kk < 4; ++kk) {
            uint32_t af[2][4], bf[4][4];
            ldsm4(af[0], aB + kk * 32);
            ldsm4(af[1], aB + kk * 32 + 16 * 528);
#pragma unroll
            for (int i = 0; i < 4; ++i) ldsm4(bf[i], bB + kk * 32 + i * 16 * 144);
#pragma unroll
            for (int ms = 0; ms < 2; ++ms)
#pragma unroll
                for (int i = 0; i < 4; ++i) {
                    mma16(acc[ms][2 * i + 0], af[ms], bf[i][0], bf[i][2]);
                    mma16(acc[ms][2 * i + 1], af[ms], bf[i][1], bf[i][3]);
                }
        }
        if (kc == 3) {
            // ==== epilogue for n-block nb via staged scratch ====
            // Barrier FIRST: all warps must finish ldsm-reading stage it%3
            // B data before any warp overwrites it with accumulators (the
            // missing barrier here was R13's correctness bug).
            __syncthreads();
            const int nb = it >> 2;
            char* stgp = smem + 67584 + (it % 3) * 36864;   // 64 x 528B used
#pragma unroll
            for (int q = 0; q < 4; ++q) {
                // --- STS phase: this thread's j in [q*16, q*16+16) of block wn
#pragma unroll
                for (int nsl = 0; nsl < 2; ++nsl) {
                    int ns = q * 2 + nsl;
                    int jc = nb * 256 + wn * 64 + ns * 8 + (lane & 3) * 2;
                    float b0 = biasS[jc], b1 = biasS[jc + 1];
                    int jp = wn * 16 + nsl * 8 + (lane & 3) * 2;
#pragma unroll
                    for (int ms = 0; ms < 2; ++ms)
#pragma unroll
                        for (int hf = 0; hf < 2; ++hf) {
                            int m_l = wm * 32 + ms * 16 + (lane >> 2) + hf * 8;
                            float v0 = fmaxf(acc[ms][ns][hf * 2 + 0] + b0, 0.f);
                            float v1 = fmaxf(acc[ms][ns][hf * 2 + 1] + b1, 0.f);
                            *(float*)(stgp + jp * 528 + m_l * 4) = v0;
                            *(float*)(stgp + (jp + 1) * 528 + m_l * 4) = v1;
                        }
                }
                // --- identity prefetch (independent of staging)
                const int cp = nb * 64 + sWn * 16 + q * 4 + sLq;
                const float* xp = x + ((long)(bb * 256 + cp)) * 25600 + rowT;
                float4 xt0 = *(const float4*)(xp);
                float4 xt1 = *(const float4*)(xp + 4);
                float4 xb0 = *(const float4*)(xp + 160);
                float4 xb1 = *(const float4*)(xp + 164);
                __syncthreads();
                // --- read quad rows, iDWT, add identity, coalesced store
                char* rbase = stgp + (warp * 4) * 528 + lane * 16;
                float4 r0 = *(const float4*)(rbase);
                float4 r1 = *(const float4*)(rbase + 528);
                float4 r2 = *(const float4*)(rbase + 1056);
                float4 r3 = *(const float4*)(rbase + 1584);
                float4 t0, t1, b0v, b1v;
                {
                    float pa = r0.x + r1.x, ra = r0.x - r1.x;
                    float pb = r2.x + r3.x, rb = r2.x - r3.x;
                    t0.x = 0.5f * (pa + pb) + xt0.x;
                    t0.y = 0.5f * (pa - pb) + xt0.y;
                    b0v.x = 0.5f * (ra + rb) + xb0.x;
                    b0v.y = 0.5f * (ra - rb) + xb0.y;
                }
                {
                    float pa = r0.y + r1.y, ra = r0.y - r1.y;
                    float pb = r2.y + r3.y, rb = r2.y - r3.y;
                    t0.z = 0.5f * (pa + pb) + xt0.z;
                    t0.w = 0.5f * (pa - pb) + xt0.w;
                    b0v.z = 0.5f * (ra + rb) + xb0.z;
                    b0v.w = 0.5f * (ra - rb) + xb0.w;
                }
                {
                    float pa = r0.z + r1.z, ra = r0.z - r1.z;
                    float pb = r2.z + r3.z, rb = r2.z - r3.z;
                    t1.x = 0.5f * (pa + pb) + xt1.x;
                    t1.y = 0.5f * (pa - pb) + xt1.y;
                    b1v.x = 0.5f * (ra + rb) + xb1.x;
                    b1v.y = 0.5f * (ra - rb) + xb1.y;
                }
                {
                    float pa = r0.w + r1.w, ra = r0.w - r1.w;
                    float pb = r2.w + r3.w, rb = r2.w - r3.w;
                    t1.z = 0.5f * (pa + pb) + xt1.z;
                    t1.w = 0.5f * (pa - pb) + xt1.w;
                    b1v.z = 0.5f * (ra + rb) + xb1.z;
                    b1v.w = 0.5f * (ra - rb) + xb1.w;
                }
                float* op = out + ((long)(bb * 256 + cp)) * 25600 + rowT;
                *(float4*)(op)       = t0;
                *(float4*)(op + 4)   = t1;
                *(float4*)(op + 160) = b0v;
                *(float4*)(op + 164) = b1v;
                __syncthreads();
            }
#pragma unroll
            for (int a = 0; a < 2; a++)
#pragma unroll
                for (int b = 0; b < 8; b++)
#pragma unroll
                    for (int c = 0; c < 4; c++) acc[a][b][c] = 0.f;
        }
    }
}

// ---------------- host launch ---------------------------------------------
extern "C" void kernel_launch(void* const* d_in, const int* in_sizes, int n_in,
                              void* d_out, int out_size) {
    (void)in_sizes; (void)n_in; (void)out_size;
    const float* x        = (const float*)d_in[0];
    const float* fusion_w = (const float*)d_in[1];
    const float* fusion_b = (const float*)d_in[2];
    const float* bn1_g    = (const float*)d_in[3];
    const float* bn1_b    = (const float*)d_in[4];
    const float* bn1_m    = (const float*)d_in[5];
    const float* bn1_v    = (const float*)d_in[6];
    const float* sa_w     = (const float*)d_in[7];
    const float* ca_w1    = (const float*)d_in[8];
    const float* ca_w2    = (const float*)d_in[9];
    const float* proj_w   = (const float*)d_in[10];
    const float* proj_b   = (const float*)d_in[11];
    const float* bn2_g    = (const float*)d_in[12];
    const float* bn2_b    = (const float*)d_in[13];
    const float* bn2_m    = (const float*)d_in[14];
    const float* bn2_v    = (const float*)d_in[15];
    float* out = (float*)d_out;

    cudaFuncSetAttribute(gemm1, cudaFuncAttributeMaxDynamicSharedMemorySize, G1_SMEM);
    cudaFuncSetAttribute(gemm2, cudaFuncAttributeMaxDynamicSharedMemorySize, G2_SMEM);

    // gemm2 stays the 4th launch -> ncu capture shows it.
    prep<<<(2 * K1 * N1) / 256, 256>>>(fusion_w, fusion_b, bn1_g, bn1_b, bn1_m, bn1_v,
                                       proj_w, proj_b, bn2_g, bn2_b, bn2_m, bn2_v);
    gemm1<<<MTOT / 128, 512, G1_SMEM>>>(x);
    spstats<<<MTOT / 256, 256>>>(sa_w);
    gemm2<<<MTOT / 128, 512, G2_SMEM>>>(x, ca_w1, ca_w2, out);
}